// round 3
// baseline (speedup 1.0000x reference)
#include <cuda_runtime.h>
#include <cstdint>

// GroupedEmbeddingBag: T tables, each with weights [V, D] fp32.
// values: [T, L] int32, offsets: [T, B+1] int32 (JAX x64 disabled -> int32!),
// out: [B, T*D] fp32.
// One warp handles one (table, bag) pair: 32 lanes x float4 = 512B = one row.

static constexpr int T = 8;
static constexpr int V = 100000;
static constexpr int D = 128;
static constexpr int B = 4096;

__global__ void __launch_bounds__(256)
grouped_embedding_bag_kernel(const int* __restrict__ values,
                             const int* __restrict__ offsets,
                             const float* __restrict__ weights,
                             float* __restrict__ out,
                             int L)
{
    const int warp = (blockIdx.x * blockDim.x + threadIdx.x) >> 5;
    const int lane = threadIdx.x & 31;
    if (warp >= T * B) return;

    // Table-major linear id: consecutive warps share a table, so each
    // table's 51.2 MB weight slab streams through L2 together.
    const int t = warp / B;
    const int b = warp - t * B;

    const int* offs = offsets + t * (B + 1);
    const int  s = offs[b];
    const int  e = offs[b + 1];

    const int* vals = values + t * L;
    const float4* __restrict__ W =
        reinterpret_cast<const float4*>(weights + (long long)t * V * D);

    float4 acc = make_float4(0.f, 0.f, 0.f, 0.f);

    int i = s;
    // 2-way unroll: two independent gathers in flight per warp.
    for (; i + 1 < e; i += 2) {
        const int v0 = vals[i];
        const int v1 = vals[i + 1];
        const float4 r0 = __ldg(&W[(long long)v0 * 32 + lane]);
        const float4 r1 = __ldg(&W[(long long)v1 * 32 + lane]);
        acc.x += r0.x; acc.y += r0.y; acc.z += r0.z; acc.w += r0.w;
        acc.x += r1.x; acc.y += r1.y; acc.z += r1.z; acc.w += r1.w;
    }
    if (i < e) {
        const int v0 = vals[i];
        const float4 r0 = __ldg(&W[(long long)v0 * 32 + lane]);
        acc.x += r0.x; acc.y += r0.y; acc.z += r0.z; acc.w += r0.w;
    }

    // out[b, t*D ...]: warp writes 512B contiguous, coalesced.
    float4* dst = reinterpret_cast<float4*>(out + (long long)b * (T * D) + t * D);
    dst[lane] = acc;
}

extern "C" void kernel_launch(void* const* d_in, const int* in_sizes, int n_in,
                              void* d_out, int out_size)
{
    const int*   values  = (const int*)d_in[0];    // [T, L] int32
    const int*   offsets = (const int*)d_in[1];    // [T, B+1] int32
    const float* weights = (const float*)d_in[2];  // [T, V, D] fp32
    float* out = (float*)d_out;                    // [B, T*D] fp32

    const int L = in_sizes[0] / T;

    const int total_warps = T * B;           // 32768
    const int threads = 256;                 // 8 warps per block
    const int blocks = (total_warps * 32 + threads - 1) / threads;  // 4096

    grouped_embedding_bag_kernel<<<blocks, threads>>>(values, offsets, weights, out, L);
}

// round 4
// speedup vs baseline: 1.9993x; 1.9993x over previous
#include <cuda_runtime.h>
#include <cstdint>

// GroupedEmbeddingBag: T tables, weights [V, D] fp32 each.
// values: [T, L] int32, offsets: [T, B+1] int32, out: [B, T*D] fp32.
// One warp per (table, bag); 32 lanes x float4 = one 512B row per gather.
// MLP=8: prefetch 8 indices, issue 8 independent row gathers before consuming.

static constexpr int T = 8;
static constexpr int V = 100000;
static constexpr int D = 128;
static constexpr int B = 4096;

__global__ void __launch_bounds__(256)
grouped_embedding_bag_kernel(const int* __restrict__ values,
                             const int* __restrict__ offsets,
                             const float* __restrict__ weights,
                             float* __restrict__ out,
                             int L)
{
    const int warp = (blockIdx.x * blockDim.x + threadIdx.x) >> 5;
    const int lane = threadIdx.x & 31;
    if (warp >= T * B) return;

    // Table-major: consecutive warps share a table, so each table's
    // 51.2 MB weight slab streams through L2 together (reuse ~2x).
    const int t = warp / B;
    const int b = warp - t * B;

    const int* offs = offsets + t * (B + 1);
    const int  s = offs[b];
    const int  e = offs[b + 1];

    const int* vals = values + t * L;
    const float4* __restrict__ W =
        reinterpret_cast<const float4*>(weights + (long long)t * V * D);

    float4 acc0 = make_float4(0.f, 0.f, 0.f, 0.f);
    float4 acc1 = make_float4(0.f, 0.f, 0.f, 0.f);

    int i = s;

    // Main loop: 8 independent gathers in flight per warp.
    for (; i + 8 <= e; i += 8) {
        int idx[8];
        #pragma unroll
        for (int j = 0; j < 8; j++) idx[j] = vals[i + j];

        float4 r[8];
        #pragma unroll
        for (int j = 0; j < 8; j++)
            r[j] = __ldg(&W[(long long)idx[j] * 32 + lane]);

        #pragma unroll
        for (int j = 0; j < 8; j += 2) {
            acc0.x += r[j].x;     acc0.y += r[j].y;
            acc0.z += r[j].z;     acc0.w += r[j].w;
            acc1.x += r[j + 1].x; acc1.y += r[j + 1].y;
            acc1.z += r[j + 1].z; acc1.w += r[j + 1].w;
        }
    }

    // Remainder (< 8 rows), still issuing independent loads.
    {
        int   idx[8];
        int   n = e - i;
        #pragma unroll
        for (int j = 0; j < 8; j++)
            idx[j] = (j < n) ? vals[i + j] : -1;

        float4 r[8];
        #pragma unroll
        for (int j = 0; j < 8; j++)
            if (idx[j] >= 0)
                r[j] = __ldg(&W[(long long)idx[j] * 32 + lane]);

        #pragma unroll
        for (int j = 0; j < 8; j++)
            if (idx[j] >= 0) {
                acc0.x += r[j].x; acc0.y += r[j].y;
                acc0.z += r[j].z; acc0.w += r[j].w;
            }
    }

    acc0.x += acc1.x; acc0.y += acc1.y; acc0.z += acc1.z; acc0.w += acc1.w;

    // out[b, t*D ...]: warp writes 512B contiguous, coalesced.
    float4* dst = reinterpret_cast<float4*>(out + (long long)b * (T * D) + t * D);
    dst[lane] = acc0;
}

extern "C" void kernel_launch(void* const* d_in, const int* in_sizes, int n_in,
                              void* d_out, int out_size)
{
    const int*   values  = (const int*)d_in[0];    // [T, L] int32
    const int*   offsets = (const int*)d_in[1];    // [T, B+1] int32
    const float* weights = (const float*)d_in[2];  // [T, V, D] fp32
    float* out = (float*)d_out;                    // [B, T*D] fp32

    const int L = in_sizes[0] / T;

    const int total_warps = T * B;           // 32768
    const int threads = 256;                 // 8 warps per block
    const int blocks = (total_warps * 32 + threads - 1) / threads;  // 4096

    grouped_embedding_bag_kernel<<<blocks, threads>>>(values, offsets, weights, out, L);
}

// round 5
// speedup vs baseline: 2.1726x; 1.0867x over previous
#include <cuda_runtime.h>
#include <cstdint>

// GroupedEmbeddingBag: T tables, weights [V, D] fp32 each.
// values: [T, L] int32, offsets: [T, B+1] int32, out: [B, T*D] fp32.
// One warp per (table, bag); 32 lanes x float4 = one 512B row per gather.
// MLP=8 in-flight row gathers per warp; 128-thread blocks for occupancy
// granularity (66 regs -> 7 blocks/SM = 28 warps vs 3x256t = 24 warps).

static constexpr int T = 8;
static constexpr int V = 100000;
static constexpr int D = 128;
static constexpr int B = 4096;

__global__ void __launch_bounds__(128)
grouped_embedding_bag_kernel(const int* __restrict__ values,
                             const int* __restrict__ offsets,
                             const float* __restrict__ weights,
                             float* __restrict__ out,
                             int L)
{
    const int warp = (blockIdx.x * blockDim.x + threadIdx.x) >> 5;
    const int lane = threadIdx.x & 31;
    if (warp >= T * B) return;

    // Table-major: consecutive warps share a table, so each table's
    // 51.2 MB weight slab streams through L2 together (reuse ~2x).
    const int t = warp / B;
    const int b = warp - t * B;

    const int* offs = offsets + t * (B + 1);
    const int  s = offs[b];
    const int  e = offs[b + 1];

    const int* vals = values + t * L;
    const float4* __restrict__ W =
        reinterpret_cast<const float4*>(weights + (long long)t * V * D);

    float4 acc0 = make_float4(0.f, 0.f, 0.f, 0.f);
    float4 acc1 = make_float4(0.f, 0.f, 0.f, 0.f);

    int i = s;

    // Main loop: 8 independent gathers in flight per warp.
    for (; i + 8 <= e; i += 8) {
        int idx[8];
        #pragma unroll
        for (int j = 0; j < 8; j++) idx[j] = vals[i + j];

        float4 r[8];
        #pragma unroll
        for (int j = 0; j < 8; j++)
            r[j] = __ldg(&W[(long long)idx[j] * 32 + lane]);

        #pragma unroll
        for (int j = 0; j < 8; j += 2) {
            acc0.x += r[j].x;     acc0.y += r[j].y;
            acc0.z += r[j].z;     acc0.w += r[j].w;
            acc1.x += r[j + 1].x; acc1.y += r[j + 1].y;
            acc1.z += r[j + 1].z; acc1.w += r[j + 1].w;
        }
    }

    // Remainder (< 8 rows), still issuing independent loads.
    {
        int idx[8];
        int n = e - i;
        #pragma unroll
        for (int j = 0; j < 8; j++)
            idx[j] = (j < n) ? vals[i + j] : -1;

        float4 r[8];
        #pragma unroll
        for (int j = 0; j < 8; j++)
            if (idx[j] >= 0)
                r[j] = __ldg(&W[(long long)idx[j] * 32 + lane]);

        #pragma unroll
        for (int j = 0; j < 8; j++)
            if (idx[j] >= 0) {
                acc0.x += r[j].x; acc0.y += r[j].y;
                acc0.z += r[j].z; acc0.w += r[j].w;
            }
    }

    acc0.x += acc1.x; acc0.y += acc1.y; acc0.z += acc1.z; acc0.w += acc1.w;

    // out[b, t*D ...]: warp writes 512B contiguous, coalesced.
    float4* dst = reinterpret_cast<float4*>(out + (long long)b * (T * D) + t * D);
    dst[lane] = acc0;
}

extern "C" void kernel_launch(void* const* d_in, const int* in_sizes, int n_in,
                              void* d_out, int out_size)
{
    const int*   values  = (const int*)d_in[0];    // [T, L] int32
    const int*   offsets = (const int*)d_in[1];    // [T, B+1] int32
    const float* weights = (const float*)d_in[2];  // [T, V, D] fp32
    float* out = (float*)d_out;                    // [B, T*D] fp32

    const int L = in_sizes[0] / T;

    const int total_warps = T * B;           // 32768
    const int threads = 128;                 // 4 warps per block
    const int blocks = (total_warps * 32 + threads - 1) / threads;  // 8192

    grouped_embedding_bag_kernel<<<blocks, threads>>>(values, offsets, weights, out, L);
}

// round 6
// speedup vs baseline: 2.2293x; 1.0261x over previous
#include <cuda_runtime.h>
#include <cstdint>

// GroupedEmbeddingBag: T tables, weights [V, D] fp32.
// values: [T, L] int32, offsets: [T, B+1] int32, out: [B, T*D] fp32.
// One warp per (table, bag). Rows are staged global->smem with cp.async
// (no register payload), pipelined via commit groups: consume group k while
// group k+1 is in flight and k+2 is being issued.

static constexpr int T = 8;
static constexpr int V = 100000;
static constexpr int D = 128;
static constexpr int B = 4096;

static constexpr int WARPS_PER_BLOCK = 4;
static constexpr int R  = 8;   // ring slots (rows) per warp, power of two
static constexpr int G  = 4;   // rows per cp.async commit group
static constexpr int NG = 2;   // groups in flight ahead of consumption

__device__ __forceinline__ void cp_async16(float4* smem_dst, const float* gsrc) {
    uint32_t s = (uint32_t)__cvta_generic_to_shared(smem_dst);
    asm volatile("cp.async.cg.shared.global [%0], [%1], 16;\n"
                 :: "r"(s), "l"(gsrc));
}

__global__ void __launch_bounds__(128)
grouped_embedding_bag_kernel(const int* __restrict__ values,
                             const int* __restrict__ offsets,
                             const float* __restrict__ weights,
                             float* __restrict__ out,
                             int L)
{
    __shared__ float4 stage[WARPS_PER_BLOCK][R][32];   // 16 KB / block

    const int warp   = (blockIdx.x * blockDim.x + threadIdx.x) >> 5;
    const int wlocal = (threadIdx.x >> 5);
    const int lane   = threadIdx.x & 31;
    if (warp >= T * B) return;

    // Table-major: consecutive warps share a table -> L2 reuse (~2x).
    const int t = warp / B;
    const int b = warp - t * B;

    const int s = offsets[t * (B + 1) + b];
    const int e = offsets[t * (B + 1) + b + 1];
    const int n = e - s;

    const int*   vals = values + t * L + s;
    const float* Wt   = weights + (long long)t * V * D;

    float4* ring = &stage[wlocal][0][0];   // [R][32] float4

    // Issue one commit group covering rows [g0, g0+G) of this bag.
    // Empty/partial groups still commit to keep group accounting constant.
    auto issue_group = [&](int g0) {
        #pragma unroll
        for (int j = 0; j < G; j++) {
            const int row = g0 + j;
            if (row < n) {
                const int idx = vals[row];
                cp_async16(&ring[(row & (R - 1)) * 32 + lane],
                           Wt + (long long)idx * D + lane * 4);
            }
        }
        asm volatile("cp.async.commit_group;\n" ::: "memory");
    };

    float4 acc = make_float4(0.f, 0.f, 0.f, 0.f);

    // Prologue: put NG groups in flight.
    issue_group(0);
    issue_group(G);

    const int total_groups = (n + G - 1) / G;
    for (int gi = 0; gi < total_groups; gi++) {
        // All but the newest group have landed -> group gi is ready.
        asm volatile("cp.async.wait_group 1;\n" ::: "memory");

        const int g0 = gi * G;
        #pragma unroll
        for (int j = 0; j < G; j++) {
            const int row = g0 + j;
            if (row < n) {
                const float4 r = ring[(row & (R - 1)) * 32 + lane];
                acc.x += r.x; acc.y += r.y; acc.z += r.z; acc.w += r.w;
            }
        }

        // Refill the slot we just drained (possibly empty past the end).
        issue_group(g0 + NG * G);
    }

    // out[b, t*D ...]: warp writes 512B contiguous, coalesced.
    float4* dst = reinterpret_cast<float4*>(out + (long long)b * (T * D) + t * D);
    dst[lane] = acc;
}

extern "C" void kernel_launch(void* const* d_in, const int* in_sizes, int n_in,
                              void* d_out, int out_size)
{
    const int*   values  = (const int*)d_in[0];    // [T, L] int32
    const int*   offsets = (const int*)d_in[1];    // [T, B+1] int32
    const float* weights = (const float*)d_in[2];  // [T, V, D] fp32
    float* out = (float*)d_out;                    // [B, T*D] fp32

    const int L = in_sizes[0] / T;

    const int total_warps = T * B;                 // 32768
    const int threads = WARPS_PER_BLOCK * 32;      // 128
    const int blocks = (total_warps * 32 + threads - 1) / threads;  // 8192

    grouped_embedding_bag_kernel<<<blocks, threads>>>(values, offsets, weights, out, L);
}